// round 3
// baseline (speedup 1.0000x reference)
#include <cuda_runtime.h>
#include <cuda_bf16.h>
#include <math.h>

// ---------------------------------------------------------------------------
// GPT-2 124M forward. All GEMMs: bf16 hi/lo split (3-pass) mma.sync tensor
// cores, operands pre-split to bf16 pairs in gmem, cp.async pipelines.
// B=4, T=1024, C=768, NH=12, HD=64, NL=12, V=50257
// ---------------------------------------------------------------------------

#define BB   4
#define TT   1024
#define BT   4096
#define CC   768
#define C3   2304
#define C4   3072
#define NHH  12
#define HDD  64
#define NLYR 12
#define VV   50257
#define BHN  48

typedef __nv_bfloat16 bf16;

// fp32 scratch
__device__ float g_x  [(size_t)BT * CC];
__device__ float g_att[(size_t)BHN * TT * TT];
__device__ float g_nll[BT];
// activation hi/lo pairs
__device__ bf16 g_h_h [(size_t)BT * CC],  g_h_l [(size_t)BT * CC];
__device__ bf16 g_q_h [(size_t)BT * C3],  g_q_l [(size_t)BT * C3];
__device__ bf16 g_p_h [(size_t)BHN * TT * TT], g_p_l [(size_t)BHN * TT * TT];
__device__ bf16 g_y_h [(size_t)BT * CC],  g_y_l [(size_t)BT * CC];
__device__ bf16 g_f_h [(size_t)BT * C4],  g_f_l [(size_t)BT * C4];
// weight hi/lo pairs
__device__ bf16 g_aw_h[(size_t)NLYR * CC * C3], g_aw_l[(size_t)NLYR * CC * C3];
__device__ bf16 g_pw_h[(size_t)NLYR * CC * CC], g_pw_l[(size_t)NLYR * CC * CC];
__device__ bf16 g_fw_h[(size_t)NLYR * CC * C4], g_fw_l[(size_t)NLYR * CC * C4];
__device__ bf16 g_f2_h[(size_t)NLYR * C4 * CC], g_f2_l[(size_t)NLYR * C4 * CC];
__device__ bf16 g_wt_h[(size_t)VV * CC],        g_wt_l[(size_t)VV * CC];

// ---------------------------------------------------------------------------
// helpers
// ---------------------------------------------------------------------------
__device__ __forceinline__ void ldsm_x4(unsigned a, unsigned* r) {
    asm volatile("ldmatrix.sync.aligned.m8n8.x4.shared.b16 {%0,%1,%2,%3},[%4];"
                 : "=r"(r[0]), "=r"(r[1]), "=r"(r[2]), "=r"(r[3]) : "r"(a));
}
__device__ __forceinline__ void ldsm_x4_t(unsigned a, unsigned* r) {
    asm volatile("ldmatrix.sync.aligned.m8n8.x4.trans.shared.b16 {%0,%1,%2,%3},[%4];"
                 : "=r"(r[0]), "=r"(r[1]), "=r"(r[2]), "=r"(r[3]) : "r"(a));
}
__device__ __forceinline__ void mma16816(float* c, const unsigned* a, const unsigned* b) {
    asm volatile("mma.sync.aligned.m16n8k16.row.col.f32.bf16.bf16.f32 "
                 "{%0,%1,%2,%3},{%4,%5,%6,%7},{%8,%9},{%0,%1,%2,%3};"
                 : "+f"(c[0]), "+f"(c[1]), "+f"(c[2]), "+f"(c[3])
                 : "r"(a[0]), "r"(a[1]), "r"(a[2]), "r"(a[3]), "r"(b[0]), "r"(b[1]));
}
__device__ __forceinline__ void cpa16(unsigned d, const void* s) {
    asm volatile("cp.async.cg.shared.global [%0],[%1],16;" :: "r"(d), "l"(s));
}
__device__ __forceinline__ void cpa16z(unsigned d, const void* s, bool v) {
    int sz = v ? 16 : 0;
    asm volatile("cp.async.cg.shared.global [%0],[%1],16,%2;" :: "r"(d), "l"(s), "r"(sz));
}
__device__ __forceinline__ void split1(float v, bf16& h, bf16& l) {
    h = __float2bfloat16_rn(v);
    l = __float2bfloat16_rn(v - __bfloat162float(h));
}
__device__ __forceinline__ float gelu_f(float u) {
    float t = 0.7978845608028654f * (u + 0.044715f * u * u * u);
    return 0.5f * u * (1.f + tanhf(t));
}

// ---------------------------------------------------------------------------
// Tensor-core GEMM, bf16 hi/lo inputs, fp32 accumulate, 3-pass.
//   NT=false: C = A[M,K] @ B[K,N];  NT=true: C = A[M,K] @ B[N,K]^T
// EPI: 0 f32 *alpha | 1 split(acc+bias) | 2 split(gelu(acc+bias))
//      3 f32 acc+bias+R | 4 split(acc)
// 256 threads, warps WARPS_M x WARPS_N, BK=32, 2-stage cp.async pipeline.
// M%BM==0, K%32==0, (NN) N%BN==0; NT N guarded.
// ---------------------------------------------------------------------------
template<int BM, int BN, int WARPS_M, int WARPS_N, int EPI, bool NT, bool SKIP>
__global__ __launch_bounds__(256, 2)
void gemm_tc(const bf16* __restrict__ Ah, const bf16* __restrict__ Al,
             const bf16* __restrict__ Bh, const bf16* __restrict__ Bl,
             const float* __restrict__ bias, const float* __restrict__ R,
             float* __restrict__ Cf, bf16* __restrict__ Ch, bf16* __restrict__ Cl,
             int M, int N, int K, int lda, int ldb, int ldc, float alpha,
             long aO, long aI, long bO, long bI, long cO, long cI, int innerCnt)
{
    constexpr int BK  = 32;
    constexpr int BKP = 40;        // A (and NT-B) row stride in els (80B)
    constexpr int BNP = BN + 8;    // NN-B row stride
    constexpr int WM = BM / WARPS_M, WN = BN / WARPS_N;
    constexpr int MI = WM / 16, NF = WN / 8, NP = NF / 2;
    constexpr int ASZ = BM * BKP;
    constexpr int BSZ = NT ? BN * BKP : BK * BNP;
    constexpr int STG = 2 * (ASZ + BSZ);   // els per stage (hi+lo both ops)

    const int m0 = blockIdx.y * BM;
    const int n0 = blockIdx.x * BN;
    if (SKIP && n0 > m0 + BM - 1) return;

    if (innerCnt > 0) {
        int z = blockIdx.z, zo = z / innerCnt, zi = z % innerCnt;
        Ah += zo * aO + zi * aI;  Al += zo * aO + zi * aI;
        Bh += zo * bO + zi * bI;  Bl += zo * bO + zi * bI;
        long co = zo * cO + zi * cI;
        if (Cf) Cf += co;
        if (Ch) { Ch += co; Cl += co; }
    }

    extern __shared__ bf16 sm[];
    const int tid = threadIdx.x, lane = tid & 31, w = tid >> 5;
    const int wm = w / WARPS_N, wn = w % WARPS_N;

    float acc[MI][NF][4];
#pragma unroll
    for (int i = 0; i < MI; i++)
#pragma unroll
        for (int j = 0; j < NF; j++)
#pragma unroll
            for (int q = 0; q < 4; q++) acc[i][j][q] = 0.f;

    auto issue = [&](int t, int s) {
        unsigned sb = (unsigned)__cvta_generic_to_shared(sm + s * STG);
        // A hi + lo: BM rows x 4 16B-chunks each
#pragma unroll
        for (int j = 0; j < (BM * 4) / 256; j++) {
            int i = tid + 256 * j;
            int r = i >> 2, c = i & 3;
            unsigned d = sb + (r * BKP + c * 8) * 2;
            size_t off = (size_t)(m0 + r) * lda + t * BK + c * 8;
            cpa16(d, Ah + off);
            cpa16(d + ASZ * 2, Al + off);
        }
        if (NT) {
#pragma unroll
            for (int j = 0; j < (BN * 4) / 256; j++) {
                int i = tid + 256 * j;
                int r = i >> 2, c = i & 3;
                bool v = (n0 + r) < N;
                unsigned d = sb + (2 * ASZ + r * BKP + c * 8) * 2;
                size_t off = (size_t)(v ? (n0 + r) : 0) * ldb + t * BK + c * 8;
                cpa16z(d, Bh + off, v);
                cpa16z(d + BSZ * 2, Bl + off, v);
            }
        } else {
#pragma unroll
            for (int j = 0; j < (BK * (BN / 8)) / 256; j++) {
                int i = tid + 256 * j;
                int r = i / (BN / 8), c = i % (BN / 8);
                unsigned d = sb + (2 * ASZ + r * BNP + c * 8) * 2;
                size_t off = (size_t)(t * BK + r) * ldb + n0 + c * 8;
                cpa16(d, Bh + off);
                cpa16(d + BSZ * 2, Bl + off);
            }
        }
        asm volatile("cp.async.commit_group;");
    };

    const int nt = K / BK;
    issue(0, 0);

    for (int t = 0; t < nt; t++) {
        if (t + 1 < nt) {
            issue(t + 1, (t + 1) & 1);
            asm volatile("cp.async.wait_group 1;");
        } else {
            asm volatile("cp.async.wait_group 0;");
        }
        __syncthreads();

        unsigned sAh = (unsigned)__cvta_generic_to_shared(sm + (t & 1) * STG);
        unsigned sAl = sAh + ASZ * 2;
        unsigned sBh = sAh + 2 * ASZ * 2;
        unsigned sBl = sBh + BSZ * 2;

#pragma unroll
        for (int kk = 0; kk < 2; kk++) {
            unsigned a_h[MI][4], a_l[MI][4];
            const int arow = lane & 15;
            const int acol = kk * 16 + (lane >> 4) * 8;
#pragma unroll
            for (int mi = 0; mi < MI; mi++) {
                unsigned off = ((wm * WM + mi * 16 + arow) * BKP + acol) * 2;
                ldsm_x4(sAh + off, a_h[mi]);
                ldsm_x4(sAl + off, a_l[mi]);
            }
#pragma unroll
            for (int p = 0; p < NP; p++) {
                unsigned b_h[4], b_l[4];
                if (NT) {
                    const int nrow = (lane & 7) | ((lane >> 4) << 3);
                    const int kcol = kk * 16 + ((lane >> 3) & 1) * 8;
                    unsigned off = ((wn * WN + p * 16 + nrow) * BKP + kcol) * 2;
                    ldsm_x4(sBh + off, b_h);
                    ldsm_x4(sBl + off, b_l);
                } else {
                    const int krow = kk * 16 + (lane & 15);
                    const int ncol = wn * WN + p * 16 + (lane >> 4) * 8;
                    unsigned off = (krow * BNP + ncol) * 2;
                    ldsm_x4_t(sBh + off, b_h);
                    ldsm_x4_t(sBl + off, b_l);
                }
#pragma unroll
                for (int mi = 0; mi < MI; mi++) {
                    mma16816(acc[mi][2 * p],     a_h[mi], b_h);
                    mma16816(acc[mi][2 * p],     a_h[mi], b_l);
                    mma16816(acc[mi][2 * p],     a_l[mi], b_h);
                    mma16816(acc[mi][2 * p + 1], a_h[mi], b_h + 2);
                    mma16816(acc[mi][2 * p + 1], a_h[mi], b_l + 2);
                    mma16816(acc[mi][2 * p + 1], a_l[mi], b_h + 2);
                }
            }
        }
        __syncthreads();
    }

    // epilogue
    const int g = lane >> 2, tg = lane & 3;
#pragma unroll
    for (int mi = 0; mi < MI; mi++) {
#pragma unroll
        for (int nf = 0; nf < NF; nf++) {
            int col = n0 + wn * WN + nf * 8 + tg * 2;
#pragma unroll
            for (int h = 0; h < 2; h++) {
                int row = m0 + wm * WM + mi * 16 + g + h * 8;
                float v0 = acc[mi][nf][2 * h];
                float v1 = acc[mi][nf][2 * h + 1];
                if (EPI == 0) {
                    v0 *= alpha; v1 *= alpha;
                    if (col     < N) Cf[(size_t)row * ldc + col]     = v0;
                    if (col + 1 < N) Cf[(size_t)row * ldc + col + 1] = v1;
                } else if (EPI == 3) {
                    size_t o = (size_t)row * ldc + col;
                    Cf[o]     = v0 + bias[col]     + R[o];
                    Cf[o + 1] = v1 + bias[col + 1] + R[o + 1];
                } else {
                    if (EPI == 1 || EPI == 2) { v0 += bias[col]; v1 += bias[col + 1]; }
                    if (EPI == 2) { v0 = gelu_f(v0); v1 = gelu_f(v1); }
                    bf16 h0, l0, h1, l1;
                    split1(v0, h0, l0); split1(v1, h1, l1);
                    size_t o = (size_t)row * ldc + col;
                    *(__nv_bfloat162*)&Ch[o] = __nv_bfloat162(h0, h1);
                    *(__nv_bfloat162*)&Cl[o] = __nv_bfloat162(l0, l1);
                }
            }
        }
    }
}

// ---------------------------------------------------------------------------
// split fp32 array -> bf16 hi/lo pair (n % 4 == 0)
// ---------------------------------------------------------------------------
__global__ void split_arr(const float* __restrict__ s, bf16* __restrict__ h,
                          bf16* __restrict__ l, long n)
{
    long i = ((long)blockIdx.x * blockDim.x + threadIdx.x) * 4;
    if (i >= n) return;
    float4 v = *(const float4*)(s + i);
    bf16 hh[4], ll[4];
    split1(v.x, hh[0], ll[0]); split1(v.y, hh[1], ll[1]);
    split1(v.z, hh[2], ll[2]); split1(v.w, hh[3], ll[3]);
    *(uint2*)(h + i) = *(uint2*)hh;
    *(uint2*)(l + i) = *(uint2*)ll;
}

// ---------------------------------------------------------------------------
// LayerNorm: fp32 in, bf16 hi/lo out. One block per row.
// ---------------------------------------------------------------------------
__global__ void layernorm_k(const float* __restrict__ x, const float* __restrict__ g,
                            const float* __restrict__ b,
                            bf16* __restrict__ yh, bf16* __restrict__ yl)
{
    const int row = blockIdx.x;
    const float* xr = x + (size_t)row * CC;
    __shared__ float s1[256], s2[256];
    const int tid = threadIdx.x;
    float a = 0.f, sq = 0.f;
    for (int c = tid; c < CC; c += 256) { float v = xr[c]; a += v; sq += v * v; }
    s1[tid] = a; s2[tid] = sq; __syncthreads();
    for (int s = 128; s > 0; s >>= 1) {
        if (tid < s) { s1[tid] += s1[tid + s]; s2[tid] += s2[tid + s]; }
        __syncthreads();
    }
    const float mean = s1[0] / CC;
    const float var  = s2[0] / CC - mean * mean;
    const float rstd = rsqrtf(var + 1e-5f);
    for (int c = tid; c < CC; c += 256) {
        float v = (xr[c] - mean) * rstd * g[c] + b[c];
        bf16 hh, ll; split1(v, hh, ll);
        yh[(size_t)row * CC + c] = hh;
        yl[(size_t)row * CC + c] = ll;
    }
}

// ---------------------------------------------------------------------------
// Causal softmax: fp32 scores in, bf16 hi/lo probs out (zeros beyond diag).
// ---------------------------------------------------------------------------
__global__ void softmax_causal(const float* __restrict__ att,
                               bf16* __restrict__ ph, bf16* __restrict__ pl)
{
    const int t = blockIdx.x;
    const size_t ro = ((size_t)blockIdx.y * TT + t) * TT;
    const float* row = att + ro;
    const int n = t + 1;
    __shared__ float red[256];
    const int tid = threadIdx.x;

    float mx = -1e30f;
    for (int j = tid; j < n; j += 256) mx = fmaxf(mx, row[j]);
    red[tid] = mx; __syncthreads();
    for (int s = 128; s > 0; s >>= 1) {
        if (tid < s) red[tid] = fmaxf(red[tid], red[tid + s]);
        __syncthreads();
    }
    mx = red[0]; __syncthreads();

    float sum = 0.f;
    for (int j = tid; j < n; j += 256) sum += expf(row[j] - mx);
    red[tid] = sum; __syncthreads();
    for (int s = 128; s > 0; s >>= 1) {
        if (tid < s) red[tid] += red[tid + s];
        __syncthreads();
    }
    const float inv = 1.f / red[0];

    for (int j = tid; j < n; j += 256) {
        float p = expf(row[j] - mx) * inv;
        bf16 hh, ll; split1(p, hh, ll);
        ph[ro + j] = hh; pl[ro + j] = ll;
    }
    const bf16 z = __float2bfloat16(0.f);
    for (int j = n + tid; j < TT; j += 256) { ph[ro + j] = z; pl[ro + j] = z; }
}

__global__ void embed_k(const int* __restrict__ tok, const float* __restrict__ wte,
                        const float* __restrict__ wpe, float* __restrict__ x)
{
    const int idx = blockIdx.x * blockDim.x + threadIdx.x;
    if (idx >= BT * CC) return;
    const int bt = idx / CC, c = idx % CC;
    const int t  = bt % TT;
    x[idx] = wte[(size_t)tok[bt] * CC + c] + wpe[(size_t)t * CC + c];
}

__global__ void nll_k(const float* __restrict__ logits, const int* __restrict__ target,
                      float* __restrict__ nll)
{
    const int bt = blockIdx.x;
    const float* row = logits + (size_t)bt * VV;
    __shared__ float red[256];
    const int tid = threadIdx.x;

    float mx = -1e30f;
    for (int j = tid; j < VV; j += 256) mx = fmaxf(mx, row[j]);
    red[tid] = mx; __syncthreads();
    for (int s = 128; s > 0; s >>= 1) {
        if (tid < s) red[tid] = fmaxf(red[tid], red[tid + s]);
        __syncthreads();
    }
    mx = red[0]; __syncthreads();

    float sum = 0.f;
    for (int j = tid; j < VV; j += 256) sum += expf(row[j] - mx);
    red[tid] = sum; __syncthreads();
    for (int s = 128; s > 0; s >>= 1) {
        if (tid < s) red[tid] += red[tid + s];
        __syncthreads();
    }
    if (tid == 0)
        nll[bt] = logf(red[0]) + mx - row[target[bt]];
}

__global__ void mean_k(const float* __restrict__ nll, float* __restrict__ out)
{
    __shared__ float red[256];
    const int tid = threadIdx.x;
    float s = 0.f;
    for (int i = tid; i < BT; i += 256) s += nll[i];
    red[tid] = s; __syncthreads();
    for (int st = 128; st > 0; st >>= 1) {
        if (tid < st) red[tid] += red[tid + st];
        __syncthreads();
    }
    if (tid == 0) out[0] = red[0] / (float)BT;
}

// ---------------------------------------------------------------------------
// Launch
// ---------------------------------------------------------------------------
// kernel instantiation aliases
#define QKV_K   gemm_tc<128,128,2,4,1,false,false>
#define SCORE_K gemm_tc<128,128,2,4,0,true ,true >
#define PV_K    gemm_tc<128, 64,4,2,4,false,false>
#define RES_K   gemm_tc<128,128,2,4,3,false,false>
#define FC_K    gemm_tc<128,128,2,4,2,false,false>
#define LM_K    gemm_tc<128,128,2,4,0,true ,false>

static int smem_nn_128() { return 2 * 2 * (128 * 40 + 32 * 136) * 2; }   // 75776
static int smem_nt_128() { return 2 * 2 * (128 * 40 + 128 * 40) * 2; }   // 81920
static int smem_nn_64()  { return 2 * 2 * (128 * 40 + 32 * 72) * 2;  }   // 59392

extern "C" void kernel_launch(void* const* d_in, const int* in_sizes, int n_in,
                              void* d_out, int out_size)
{
    const int*   tokens = (const int*)  d_in[0];
    const int*   target = (const int*)  d_in[1];
    const float* wte    = (const float*)d_in[2];
    const float* wpe    = (const float*)d_in[3];
    const float* ln1_g  = (const float*)d_in[4];
    const float* ln1_b  = (const float*)d_in[5];
    const float* attn_w = (const float*)d_in[6];
    const float* attn_b = (const float*)d_in[7];
    const float* proj_w = (const float*)d_in[8];
    const float* proj_b = (const float*)d_in[9];
    const float* ln2_g  = (const float*)d_in[10];
    const float* ln2_b  = (const float*)d_in[11];
    const float* fc_w   = (const float*)d_in[12];
    const float* fc_b   = (const float*)d_in[13];
    const float* fc2_w  = (const float*)d_in[14];
    const float* fc2_b  = (const float*)d_in[15];
    const float* lnf_g  = (const float*)d_in[16];
    const float* lnf_b  = (const float*)d_in[17];
    float* out = (float*)d_out;

    static bool attr_done = false;
    if (!attr_done) {
        cudaFuncSetAttribute(QKV_K,   cudaFuncAttributeMaxDynamicSharedMemorySize, smem_nn_128());
        cudaFuncSetAttribute(SCORE_K, cudaFuncAttributeMaxDynamicSharedMemorySize, smem_nt_128());
        cudaFuncSetAttribute(PV_K,    cudaFuncAttributeMaxDynamicSharedMemorySize, smem_nn_64());
        cudaFuncSetAttribute(RES_K,   cudaFuncAttributeMaxDynamicSharedMemorySize, smem_nn_128());
        cudaFuncSetAttribute(FC_K,    cudaFuncAttributeMaxDynamicSharedMemorySize, smem_nn_128());
        cudaFuncSetAttribute(LM_K,    cudaFuncAttributeMaxDynamicSharedMemorySize, smem_nt_128());
        attr_done = true;
    }

    float *x, *att, *nll;
    bf16 *h_h, *h_l, *q_h, *q_l, *p_h, *p_l, *y_h, *y_l, *f_h, *f_l;
    bf16 *aw_h, *aw_l, *pw_h, *pw_l, *fw_h, *fw_l, *f2_h, *f2_l, *wt_h, *wt_l;
    cudaGetSymbolAddress((void**)&x,    g_x);
    cudaGetSymbolAddress((void**)&att,  g_att);
    cudaGetSymbolAddress((void**)&nll,  g_nll);
    cudaGetSymbolAddress((void**)&h_h,  g_h_h);  cudaGetSymbolAddress((void**)&h_l,  g_h_l);
    cudaGetSymbolAddress((void**)&q_h,  g_q_h);  cudaGetSymbolAddress((void**)&q_l,  g_q_l);
    cudaGetSymbolAddress((void**)&p_h,  g_p_h);  cudaGetSymbolAddress((void**)&p_l,  g_p_l);
    cudaGetSymbolAddress((void**)&y_h,  g_y_h);  cudaGetSymbolAddress((void**)&y_l,  g_y_l);
    cudaGetSymbolAddress((void**)&f_h,  g_f_h);  cudaGetSymbolAddress((void**)&f_l,  g_f_l);
    cudaGetSymbolAddress((void**)&aw_h, g_aw_h); cudaGetSymbolAddress((void**)&aw_l, g_aw_l);
    cudaGetSymbolAddress((void**)&pw_h, g_pw_h); cudaGetSymbolAddress((void**)&pw_l, g_pw_l);
    cudaGetSymbolAddress((void**)&fw_h, g_fw_h); cudaGetSymbolAddress((void**)&fw_l, g_fw_l);
    cudaGetSymbolAddress((void**)&f2_h, g_f2_h); cudaGetSymbolAddress((void**)&f2_l, g_f2_l);
    cudaGetSymbolAddress((void**)&wt_h, g_wt_h); cudaGetSymbolAddress((void**)&wt_l, g_wt_l);

    // pre-split weights to bf16 hi/lo
    {
        long n1 = (long)NLYR * CC * C3;
        long n2 = (long)NLYR * CC * CC;
        long n3 = (long)NLYR * CC * C4;
        long n5 = (long)VV * CC;
        split_arr<<<(unsigned)((n1/4 + 255)/256), 256>>>(attn_w, aw_h, aw_l, n1);
        split_arr<<<(unsigned)((n2/4 + 255)/256), 256>>>(proj_w, pw_h, pw_l, n2);
        split_arr<<<(unsigned)((n3/4 + 255)/256), 256>>>(fc_w,   fw_h, fw_l, n3);
        split_arr<<<(unsigned)((n3/4 + 255)/256), 256>>>(fc2_w,  f2_h, f2_l, n3);
        split_arr<<<(unsigned)((n5/4 + 255)/256), 256>>>(wte,    wt_h, wt_l, n5);
    }

    embed_k<<<(BT * CC + 255) / 256, 256>>>(tokens, wte, wpe, x);

    const long L1M = (long)TT * TT;
    const long QB  = (long)TT * C3;

    for (int l = 0; l < NLYR; l++) {
        const bf16* lawh = aw_h + (size_t)l * CC * C3;
        const bf16* lawl = aw_l + (size_t)l * CC * C3;
        const bf16* lpwh = pw_h + (size_t)l * CC * CC;
        const bf16* lpwl = pw_l + (size_t)l * CC * CC;
        const bf16* lfwh = fw_h + (size_t)l * CC * C4;
        const bf16* lfwl = fw_l + (size_t)l * CC * C4;
        const bf16* lf2h = f2_h + (size_t)l * C4 * CC;
        const bf16* lf2l = f2_l + (size_t)l * C4 * CC;
        const float* ab  = attn_b + (size_t)l * C3;
        const float* pb  = proj_b + (size_t)l * CC;
        const float* fb  = fc_b   + (size_t)l * C4;
        const float* f2b = fc2_b  + (size_t)l * CC;

        layernorm_k<<<BT, 256>>>(x, ln1_g + l * CC, ln1_b + l * CC, h_h, h_l);

        // QKV -> split qkv
        QKV_K<<<dim3(C3/128, BT/128), 256, smem_nn_128()>>>(
            h_h, h_l, lawh, lawl, ab, nullptr, nullptr, q_h, q_l,
            BT, C3, CC, CC, C3, C3, 1.f, 0,0,0,0,0,0, 0);

        // scores (f32), causal skip, batched over 48 heads
        SCORE_K<<<dim3(TT/128, TT/128, BHN), 256, smem_nt_128()>>>(
            q_h, q_l, q_h + CC, q_l + CC, nullptr, nullptr, att, nullptr, nullptr,
            TT, TT, HDD, C3, C3, TT, 0.125f,
            QB, HDD, QB, HDD, (long)NHH * L1M, L1M, NHH);

        softmax_causal<<<dim3(TT, BHN), 256>>>(att, p_h, p_l);

        // y = P @ V  -> split y
        PV_K<<<dim3(1, TT/128, BHN), 256, smem_nn_64()>>>(
            p_h, p_l, q_h + 2 * CC, q_l + 2 * CC, nullptr, nullptr,
            nullptr, y_h, y_l, TT, HDD, TT, TT, C3, CC, 1.f,
            (long)NHH * L1M, L1M, QB, HDD, (long)TT * CC, HDD, NHH);

        // x = x + y @ pw + pb   (f32 residual)
        RES_K<<<dim3(CC/128, BT/128), 256, smem_nn_128()>>>(
            y_h, y_l, lpwh, lpwl, pb, x, x, nullptr, nullptr,
            BT, CC, CC, CC, CC, CC, 1.f, 0,0,0,0,0,0, 0);

        layernorm_k<<<BT, 256>>>(x, ln2_g + l * CC, ln2_b + l * CC, h_h, h_l);

        // fc + gelu -> split fc
        FC_K<<<dim3(C4/128, BT/128), 256, smem_nn_128()>>>(
            h_h, h_l, lfwh, lfwl, fb, nullptr, nullptr, f_h, f_l,
            BT, C4, CC, CC, C4, C4, 1.f, 0,0,0,0,0,0, 0);

        // x = x + fc @ f2w + f2b
        RES_K<<<dim3(CC/128, BT/128), 256, smem_nn_128()>>>(
            f_h, f_l, lf2h, lf2l, f2b, x, x, nullptr, nullptr,
            BT, CC, C4, C4, CC, CC, 1.f, 0,0,0,0,0,0, 0);
    }

    layernorm_k<<<BT, 256>>>(x, lnf_g, lnf_b, h_h, h_l);

    // logits = h @ wte^T (f32 out)
    LM_K<<<dim3((VV + 127) / 128, BT / 128), 256, smem_nt_128()>>>(
        h_h, h_l, wt_h, wt_l, nullptr, nullptr, out, nullptr, nullptr,
        BT, VV, CC, CC, CC, VV, 1.f, 0,0,0,0,0,0, 0);

    nll_k<<<BT, 256>>>(out, target, nll);
    mean_k<<<1, 256>>>(nll, out + (out_size - 1));
}

// round 9
// speedup vs baseline: 2.2529x; 2.2529x over previous
#include <cuda_runtime.h>
#include <cuda_fp16.h>
#include <math.h>

// ---------------------------------------------------------------------------
// GPT-2 124M forward. All GEMMs: single-pass fp16 mma.sync (fp32 accum),
// operands pre-converted to fp16 in gmem. fp32 residual/LN/softmax math.
// B=4, T=1024, C=768, NH=12, HD=64, NL=12, V=50257
// ---------------------------------------------------------------------------

#define BB   4
#define TT   1024
#define BT   4096
#define CC   768
#define C3   2304
#define C4   3072
#define NHH  12
#define HDD  64
#define NLYR 12
#define VV   50257
#define BHN  48

typedef __half h16;

// fp32 scratch
__device__ float g_x  [(size_t)BT * CC];
__device__ float g_att[(size_t)BHN * TT * TT];
__device__ float g_nll[BT];
// fp16 activations
__device__ h16 g_h [(size_t)BT * CC];
__device__ h16 g_q [(size_t)BT * C3];
__device__ h16 g_p [(size_t)BHN * TT * TT];
__device__ h16 g_y [(size_t)BT * CC];
__device__ h16 g_f [(size_t)BT * C4];
// fp16 weights
__device__ h16 g_aw[(size_t)NLYR * CC * C3];
__device__ h16 g_pw[(size_t)NLYR * CC * CC];
__device__ h16 g_fw[(size_t)NLYR * CC * C4];
__device__ h16 g_f2[(size_t)NLYR * C4 * CC];
__device__ h16 g_wt[(size_t)VV * CC];

// ---------------------------------------------------------------------------
// helpers
// ---------------------------------------------------------------------------
__device__ __forceinline__ void ldsm_x4(unsigned a, unsigned* r) {
    asm volatile("ldmatrix.sync.aligned.m8n8.x4.shared.b16 {%0,%1,%2,%3},[%4];"
                 : "=r"(r[0]), "=r"(r[1]), "=r"(r[2]), "=r"(r[3]) : "r"(a));
}
__device__ __forceinline__ void ldsm_x4_t(unsigned a, unsigned* r) {
    asm volatile("ldmatrix.sync.aligned.m8n8.x4.trans.shared.b16 {%0,%1,%2,%3},[%4];"
                 : "=r"(r[0]), "=r"(r[1]), "=r"(r[2]), "=r"(r[3]) : "r"(a));
}
__device__ __forceinline__ void mma16816(float* c, const unsigned* a, const unsigned* b) {
    asm volatile("mma.sync.aligned.m16n8k16.row.col.f32.f16.f16.f32 "
                 "{%0,%1,%2,%3},{%4,%5,%6,%7},{%8,%9},{%0,%1,%2,%3};"
                 : "+f"(c[0]), "+f"(c[1]), "+f"(c[2]), "+f"(c[3])
                 : "r"(a[0]), "r"(a[1]), "r"(a[2]), "r"(a[3]), "r"(b[0]), "r"(b[1]));
}
__device__ __forceinline__ float gelu_f(float u) {
    float t = 0.7978845608028654f * (u + 0.044715f * u * u * u);
    return 0.5f * u * (1.f + tanhf(t));
}

// ---------------------------------------------------------------------------
// Tensor-core GEMM, fp16 in, fp32 accumulate, single pass.
//   NT=false: C = A[M,K] @ B[K,N];  NT=true: C = alpha * A[M,K] @ B[N,K]^T
// EPI: 0 f32 *alpha | 1 h16(acc+bias) | 2 h16(gelu(acc+bias))
//      3 f32 acc+bias+R | 4 h16(acc)
// 256 threads, 8 warps (BM/WM)x(BN/WN), BK=16, reg-staged double buffer.
// M%BM==0, K%16==0, (NN) N%BN==0; NT N guarded.
// ---------------------------------------------------------------------------
template<int BM, int BN, int WM, int WN, int EPI, bool NT, bool SKIP>
__global__ __launch_bounds__(256)
void gemm_tc(const h16* __restrict__ A, const h16* __restrict__ B,
             const float* __restrict__ bias, const float* __restrict__ R,
             float* __restrict__ Cf, h16* __restrict__ Ch,
             int M, int N, int K, int lda, int ldb, int ldc, float alpha,
             long aO, long aI, long bO, long bI, long cO, long cI, int innerCnt)
{
    constexpr int BK  = 16;
    constexpr int BKP = 24;        // padded k row stride (48B)
    constexpr int BNP = BN + 8;    // NN B row stride
    constexpr int WARPS_N = BN / WN;
    constexpr int MI = WM / 16, NF = WN / 8, NP = NF / 2;
    constexpr int ALD = (BM * BK / 4) / 256;     // uint2 loads per thread
    constexpr int BLD = (BN * BK / 4) / 256;
    static_assert((BM / WM) * (BN / WN) == 8, "8 warps");

    const int m0 = blockIdx.y * BM;
    const int n0 = blockIdx.x * BN;
    if (SKIP && n0 > m0 + BM - 1) return;

    if (innerCnt > 0) {
        int z = blockIdx.z, zo = z / innerCnt, zi = z % innerCnt;
        A += zo * aO + zi * aI;
        B += zo * bO + zi * bI;
        long co = zo * cO + zi * cI;
        if (Cf) Cf += co;
        if (Ch) Ch += co;
    }

    constexpr int ASZ = BM * BKP;                 // els
    constexpr int BSZ = NT ? BN * BKP : BK * BNP;
    __shared__ __align__(16) h16 sm[2 * (ASZ + BSZ)];

    const int tid = threadIdx.x, lane = tid & 31, w = tid >> 5;
    const int wm = w / WARPS_N, wn = w % WARPS_N;

    float acc[MI][NF][4];
#pragma unroll
    for (int i = 0; i < MI; i++)
#pragma unroll
        for (int j = 0; j < NF; j++)
#pragma unroll
            for (int q = 0; q < 4; q++) acc[i][j][q] = 0.f;

    uint2 pa[ALD], pb[BLD];

    auto loadG = [&](int t) {
#pragma unroll
        for (int j = 0; j < ALD; j++) {
            int i = tid + 256 * j;
            int r = i >> 2, kc = (i & 3) * 4;
            pa[j] = *(const uint2*)(A + (size_t)(m0 + r) * lda + t * BK + kc);
        }
#pragma unroll
        for (int j = 0; j < BLD; j++) {
            int i = tid + 256 * j;
            if (NT) {
                int nr = i >> 2, kc = (i & 3) * 4;
                if (n0 + nr < N)
                    pb[j] = *(const uint2*)(B + (size_t)(n0 + nr) * ldb + t * BK + kc);
                else
                    pb[j] = make_uint2(0u, 0u);
            } else {
                int kk = i / (BN / 4), nc = (i % (BN / 4)) * 4;
                pb[j] = *(const uint2*)(B + (size_t)(t * BK + kk) * ldb + n0 + nc);
            }
        }
    };

    auto storeS = [&](int buf) {
        h16* As = sm + buf * (ASZ + BSZ);
        h16* Bs = As + ASZ;
#pragma unroll
        for (int j = 0; j < ALD; j++) {
            int i = tid + 256 * j;
            int r = i >> 2, kc = (i & 3) * 4;
            *(uint2*)&As[r * BKP + kc] = pa[j];
        }
#pragma unroll
        for (int j = 0; j < BLD; j++) {
            int i = tid + 256 * j;
            if (NT) {
                int nr = i >> 2, kc = (i & 3) * 4;
                *(uint2*)&Bs[nr * BKP + kc] = pb[j];
            } else {
                int kk = i / (BN / 4), nc = (i % (BN / 4)) * 4;
                *(uint2*)&Bs[kk * BNP + nc] = pb[j];
            }
        }
    };

    const int nt = K / BK;
    loadG(0);
    storeS(0);
    __syncthreads();

    for (int t = 0; t < nt; t++) {
        const int buf = t & 1;
        if (t + 1 < nt) loadG(t + 1);

        h16* As = sm + buf * (ASZ + BSZ);
        unsigned sA = (unsigned)__cvta_generic_to_shared(As);
        unsigned sB = sA + ASZ * 2;

        unsigned a[MI][4];
        {
            const int arow = lane & 15;
            const int acol = (lane >> 4) * 8;
#pragma unroll
            for (int mi = 0; mi < MI; mi++)
                ldsm_x4(sA + ((wm * WM + mi * 16 + arow) * BKP + acol) * 2, a[mi]);
        }
#pragma unroll
        for (int p = 0; p < NP; p++) {
            unsigned b[4];
            if (NT) {
                const int nrow = (lane & 7) | ((lane >> 4) << 3);
                const int kcol = ((lane >> 3) & 1) * 8;
                ldsm_x4(sB + ((wn * WN + p * 16 + nrow) * BKP + kcol) * 2, b);
            } else {
                const int krow = lane & 15;
                const int ncol = wn * WN + p * 16 + (lane >> 4) * 8;
                ldsm_x4_t(sB + (krow * BNP + ncol) * 2, b);
            }
#pragma unroll
            for (int mi = 0; mi < MI; mi++) {
                mma16816(acc[mi][2 * p],     a[mi], b);
                mma16816(acc[mi][2 * p + 1], a[mi], b + 2);
            }
        }

        if (t + 1 < nt) {
            storeS(buf ^ 1);
            __syncthreads();
        }
    }

    // epilogue
    const int g = lane >> 2, tg = lane & 3;
#pragma unroll
    for (int mi = 0; mi < MI; mi++) {
#pragma unroll
        for (int nf = 0; nf < NF; nf++) {
            int col = n0 + wn * WN + nf * 8 + tg * 2;
#pragma unroll
            for (int h = 0; h < 2; h++) {
                int row = m0 + wm * WM + mi * 16 + g + h * 8;
                float v0 = acc[mi][nf][2 * h];
                float v1 = acc[mi][nf][2 * h + 1];
                if (EPI == 0) {
                    v0 *= alpha; v1 *= alpha;
                    if (col     < N) Cf[(size_t)row * ldc + col]     = v0;
                    if (col + 1 < N) Cf[(size_t)row * ldc + col + 1] = v1;
                } else if (EPI == 3) {
                    size_t o = (size_t)row * ldc + col;
                    Cf[o]     = v0 + bias[col]     + R[o];
                    Cf[o + 1] = v1 + bias[col + 1] + R[o + 1];
                } else {
                    if (EPI == 1 || EPI == 2) { v0 += bias[col]; v1 += bias[col + 1]; }
                    if (EPI == 2) { v0 = gelu_f(v0); v1 = gelu_f(v1); }
                    size_t o = (size_t)row * ldc + col;
                    *(__half2*)&Ch[o] = __floats2half2_rn(v0, v1);
                }
            }
        }
    }
}

// ---------------------------------------------------------------------------
// fp32 -> fp16 array convert (n % 4 == 0)
// ---------------------------------------------------------------------------
__global__ void conv_arr(const float* __restrict__ s, h16* __restrict__ d, long n)
{
    long i = ((long)blockIdx.x * blockDim.x + threadIdx.x) * 4;
    if (i >= n) return;
    float4 v = *(const float4*)(s + i);
    __half2 a = __floats2half2_rn(v.x, v.y);
    __half2 b = __floats2half2_rn(v.z, v.w);
    *(uint2*)(d + i) = make_uint2(*(unsigned*)&a, *(unsigned*)&b);
}

// ---------------------------------------------------------------------------
// LayerNorm: fp32 in, fp16 out. One block per row.
// ---------------------------------------------------------------------------
__global__ void layernorm_k(const float* __restrict__ x, const float* __restrict__ g,
                            const float* __restrict__ b, h16* __restrict__ y)
{
    const int row = blockIdx.x;
    const float* xr = x + (size_t)row * CC;
    __shared__ float s1[256], s2[256];
    const int tid = threadIdx.x;
    float a = 0.f, sq = 0.f;
    for (int c = tid; c < CC; c += 256) { float v = xr[c]; a += v; sq += v * v; }
    s1[tid] = a; s2[tid] = sq; __syncthreads();
    for (int s = 128; s > 0; s >>= 1) {
        if (tid < s) { s1[tid] += s1[tid + s]; s2[tid] += s2[tid + s]; }
        __syncthreads();
    }
    const float mean = s1[0] / CC;
    const float var  = s2[0] / CC - mean * mean;
    const float rstd = rsqrtf(var + 1e-5f);
    for (int c = tid; c < CC; c += 256)
        y[(size_t)row * CC + c] = __float2half_rn((xr[c] - mean) * rstd * g[c] + b[c]);
}

// ---------------------------------------------------------------------------
// Causal softmax: fp32 scores in, fp16 probs out (zeros beyond diagonal).
// ---------------------------------------------------------------------------
__global__ void softmax_causal(const float* __restrict__ att, h16* __restrict__ p)
{
    const int t = blockIdx.x;
    const size_t ro = ((size_t)blockIdx.y * TT + t) * TT;
    const float* row = att + ro;
    const int n = t + 1;
    __shared__ float red[256];
    const int tid = threadIdx.x;

    float mx = -1e30f;
    for (int j = tid; j < n; j += 256) mx = fmaxf(mx, row[j]);
    red[tid] = mx; __syncthreads();
    for (int s = 128; s > 0; s >>= 1) {
        if (tid < s) red[tid] = fmaxf(red[tid], red[tid + s]);
        __syncthreads();
    }
    mx = red[0]; __syncthreads();

    float sum = 0.f;
    for (int j = tid; j < n; j += 256) sum += expf(row[j] - mx);
    red[tid] = sum; __syncthreads();
    for (int s = 128; s > 0; s >>= 1) {
        if (tid < s) red[tid] += red[tid + s];
        __syncthreads();
    }
    const float inv = 1.f / red[0];

    for (int j = tid; j < n; j += 256)
        p[ro + j] = __float2half_rn(expf(row[j] - mx) * inv);
    const h16 z = __float2half(0.f);
    for (int j = n + tid; j < TT; j += 256) p[ro + j] = z;
}

__global__ void embed_k(const int* __restrict__ tok, const float* __restrict__ wte,
                        const float* __restrict__ wpe, float* __restrict__ x)
{
    const int idx = blockIdx.x * blockDim.x + threadIdx.x;
    if (idx >= BT * CC) return;
    const int bt = idx / CC, c = idx % CC;
    const int t  = bt % TT;
    x[idx] = wte[(size_t)tok[bt] * CC + c] + wpe[(size_t)t * CC + c];
}

__global__ void nll_k(const float* __restrict__ logits, const int* __restrict__ target,
                      float* __restrict__ nll)
{
    const int bt = blockIdx.x;
    const float* row = logits + (size_t)bt * VV;
    __shared__ float red[256];
    const int tid = threadIdx.x;

    float mx = -1e30f;
    for (int j = tid; j < VV; j += 256) mx = fmaxf(mx, row[j]);
    red[tid] = mx; __syncthreads();
    for (int s = 128; s > 0; s >>= 1) {
        if (tid < s) red[tid] = fmaxf(red[tid], red[tid + s]);
        __syncthreads();
    }
    mx = red[0]; __syncthreads();

    float sum = 0.f;
    for (int j = tid; j < VV; j += 256) sum += expf(row[j] - mx);
    red[tid] = sum; __syncthreads();
    for (int s = 128; s > 0; s >>= 1) {
        if (tid < s) red[tid] += red[tid + s];
        __syncthreads();
    }
    if (tid == 0)
        nll[bt] = logf(red[0]) + mx - row[target[bt]];
}

__global__ void mean_k(const float* __restrict__ nll, float* __restrict__ out)
{
    __shared__ float red[256];
    const int tid = threadIdx.x;
    float s = 0.f;
    for (int i = tid; i < BT; i += 256) s += nll[i];
    red[tid] = s; __syncthreads();
    for (int st = 128; st > 0; st >>= 1) {
        if (tid < st) red[tid] += red[tid + st];
        __syncthreads();
    }
    if (tid == 0) out[0] = red[0] / (float)BT;
}

// ---------------------------------------------------------------------------
// Launch
// ---------------------------------------------------------------------------
extern "C" void kernel_launch(void* const* d_in, const int* in_sizes, int n_in,
                              void* d_out, int out_size)
{
    const int*   tokens = (const int*)  d_in[0];
    const int*   target = (const int*)  d_in[1];
    const float* wte    = (const float*)d_in[2];
    const float* wpe    = (const float*)d_in[3];
    const float* ln1_g  = (const float*)d_in[4];
    const float* ln1_b  = (const float*)d_in[5];
    const float* attn_w = (const float*)d_in[6];
    const float* attn_b = (const float*)d_in[7];
    const float* proj_w = (const float*)d_in[8];
    const float* proj_b = (const float*)d_in[9];
    const float* ln2_g  = (const float*)d_in[10];
    const float* ln2_b  = (const float*)d_in[11];
    const float* fc_w   = (const float*)d_in[12];
    const float* fc_b   = (const float*)d_in[13];
    const float* fc2_w  = (const float*)d_in[14];
    const float* fc2_b  = (const float*)d_in[15];
    const float* lnf_g  = (const float*)d_in[16];
    const float* lnf_b  = (const float*)d_in[17];
    float* out = (float*)d_out;

    float *x, *att, *nll;
    h16 *h, *q, *p, *y, *f, *aw, *pw, *fw, *f2, *wt;
    cudaGetSymbolAddress((void**)&x,   g_x);
    cudaGetSymbolAddress((void**)&att, g_att);
    cudaGetSymbolAddress((void**)&nll, g_nll);
    cudaGetSymbolAddress((void**)&h,   g_h);
    cudaGetSymbolAddress((void**)&q,   g_q);
    cudaGetSymbolAddress((void**)&p,   g_p);
    cudaGetSymbolAddress((void**)&y,   g_y);
    cudaGetSymbolAddress((void**)&f,   g_f);
    cudaGetSymbolAddress((void**)&aw,  g_aw);
    cudaGetSymbolAddress((void**)&pw,  g_pw);
    cudaGetSymbolAddress((void**)&fw,  g_fw);
    cudaGetSymbolAddress((void**)&f2,  g_f2);
    cudaGetSymbolAddress((void**)&wt,  g_wt);

    // convert weights to fp16 (each launch; ~160us)
    {
        long n1 = (long)NLYR * CC * C3;
        long n2 = (long)NLYR * CC * CC;
        long n3 = (long)NLYR * CC * C4;
        long n5 = (long)VV * CC;
        conv_arr<<<(unsigned)((n1/4 + 255)/256), 256>>>(attn_w, aw, n1);
        conv_arr<<<(unsigned)((n2/4 + 255)/256), 256>>>(proj_w, pw, n2);
        conv_arr<<<(unsigned)((n3/4 + 255)/256), 256>>>(fc_w,   fw, n3);
        conv_arr<<<(unsigned)((n3/4 + 255)/256), 256>>>(fc2_w,  f2, n3);
        conv_arr<<<(unsigned)((n5/4 + 255)/256), 256>>>(wte,    wt, n5);
    }

    embed_k<<<(BT * CC + 255) / 256, 256>>>(tokens, wte, wpe, x);

    const long L1M = (long)TT * TT;
    const long QB  = (long)TT * C3;

    for (int l = 0; l < NLYR; l++) {
        const h16* law = aw + (size_t)l * CC * C3;
        const h16* lpw = pw + (size_t)l * CC * CC;
        const h16* lfw = fw + (size_t)l * CC * C4;
        const h16* lf2 = f2 + (size_t)l * C4 * CC;
        const float* ab  = attn_b + (size_t)l * C3;
        const float* pb  = proj_b + (size_t)l * CC;
        const float* fb  = fc_b   + (size_t)l * C4;
        const float* f2b = fc2_b  + (size_t)l * CC;

        layernorm_k<<<BT, 256>>>(x, ln1_g + l * CC, ln1_b + l * CC, h);

        // QKV -> fp16 qkv
        gemm_tc<128,128,32,64,1,false,false><<<dim3(C3/128, BT/128), 256>>>(
            h, law, ab, nullptr, nullptr, q,
            BT, C3, CC, CC, C3, C3, 1.f, 0,0,0,0,0,0, 0);

        // scores (f32), causal block skip, batched over 48 heads
        gemm_tc<128,128,32,64,0,true,true><<<dim3(TT/128, TT/128, BHN), 256>>>(
            q, q + CC, nullptr, nullptr, att, nullptr,
            TT, TT, HDD, C3, C3, TT, 0.125f,
            QB, HDD, QB, HDD, (long)NHH * L1M, L1M, NHH);

        softmax_causal<<<dim3(TT, BHN), 256>>>(att, p);

        // y = P @ V  -> fp16 y
        gemm_tc<128,64,32,32,4,false,false><<<dim3(1, TT/128, BHN), 256>>>(
            p, q + 2 * CC, nullptr, nullptr, nullptr, y,
            TT, HDD, TT, TT, C3, CC, 1.f,
            (long)NHH * L1M, L1M, QB, HDD, (long)TT * CC, HDD, NHH);

        // x = x + y @ pw + pb   (f32 residual)
        gemm_tc<128,128,32,64,3,false,false><<<dim3(CC/128, BT/128), 256>>>(
            y, lpw, pb, x, x, nullptr,
            BT, CC, CC, CC, CC, CC, 1.f, 0,0,0,0,0,0, 0);

        layernorm_k<<<BT, 256>>>(x, ln2_g + l * CC, ln2_b + l * CC, h);

        // fc + gelu -> fp16 fc
        gemm_tc<128,128,32,64,2,false,false><<<dim3(C4/128, BT/128), 256>>>(
            h, lfw, fb, nullptr, nullptr, f,
            BT, C4, CC, CC, C4, C4, 1.f, 0,0,0,0,0,0, 0);

        // x = x + fc @ f2w + f2b
        gemm_tc<128,128,32,64,3,false,false><<<dim3(CC/128, BT/128), 256>>>(
            f, lf2, f2b, x, x, nullptr,
            BT, CC, C4, C4, CC, CC, 1.f, 0,0,0,0,0,0, 0);
    }

    layernorm_k<<<BT, 256>>>(x, lnf_g, lnf_b, h);

    // logits = h @ wte^T (f32 out)
    gemm_tc<128,128,32,64,0,true,false><<<dim3((VV + 127) / 128, BT / 128), 256>>>(
        h, wt, nullptr, nullptr, out, nullptr,
        BT, VV, CC, CC, CC, VV, 1.f, 0,0,0,0,0,0, 0);

    nll_k<<<BT, 256>>>(out, target, nll);
    mean_k<<<1, 256>>>(nll, out + (out_size - 1));
}

// round 12
// speedup vs baseline: 2.3630x; 1.0489x over previous
#include <cuda_runtime.h>
#include <cuda_fp16.h>
#include <math.h>

// ---------------------------------------------------------------------------
// GPT-2 124M forward. All GEMMs: single-pass fp16 mma.sync (fp32 accum),
// operands pre-converted to fp16 in gmem. fp32 residual/LN/softmax math.
// R10: 2 CTAs/SM on gemm_tc (16 warps/SM), causal K-limit on PV GEMM.
// B=4, T=1024, C=768, NH=12, HD=64, NL=12, V=50257
// ---------------------------------------------------------------------------

#define BB   4
#define TT   1024
#define BT   4096
#define CC   768
#define C3   2304
#define C4   3072
#define NHH  12
#define HDD  64
#define NLYR 12
#define VV   50257
#define BHN  48

typedef __half h16;

// fp32 scratch
__device__ float g_x  [(size_t)BT * CC];
__device__ float g_att[(size_t)BHN * TT * TT];
__device__ float g_nll[BT];
// fp16 activations
__device__ h16 g_h [(size_t)BT * CC];
__device__ h16 g_q [(size_t)BT * C3];
__device__ h16 g_p [(size_t)BHN * TT * TT];
__device__ h16 g_y [(size_t)BT * CC];
__device__ h16 g_f [(size_t)BT * C4];
// fp16 weights
__device__ h16 g_aw[(size_t)NLYR * CC * C3];
__device__ h16 g_pw[(size_t)NLYR * CC * CC];
__device__ h16 g_fw[(size_t)NLYR * CC * C4];
__device__ h16 g_f2[(size_t)NLYR * C4 * CC];
__device__ h16 g_wt[(size_t)VV * CC];

// ---------------------------------------------------------------------------
// helpers
// ---------------------------------------------------------------------------
__device__ __forceinline__ void ldsm_x4(unsigned a, unsigned* r) {
    asm volatile("ldmatrix.sync.aligned.m8n8.x4.shared.b16 {%0,%1,%2,%3},[%4];"
                 : "=r"(r[0]), "=r"(r[1]), "=r"(r[2]), "=r"(r[3]) : "r"(a));
}
__device__ __forceinline__ void ldsm_x4_t(unsigned a, unsigned* r) {
    asm volatile("ldmatrix.sync.aligned.m8n8.x4.trans.shared.b16 {%0,%1,%2,%3},[%4];"
                 : "=r"(r[0]), "=r"(r[1]), "=r"(r[2]), "=r"(r[3]) : "r"(a));
}
__device__ __forceinline__ void mma16816(float* c, const unsigned* a, const unsigned* b) {
    asm volatile("mma.sync.aligned.m16n8k16.row.col.f32.f16.f16.f32 "
                 "{%0,%1,%2,%3},{%4,%5,%6,%7},{%8,%9},{%0,%1,%2,%3};"
                 : "+f"(c[0]), "+f"(c[1]), "+f"(c[2]), "+f"(c[3])
                 : "r"(a[0]), "r"(a[1]), "r"(a[2]), "r"(a[3]), "r"(b[0]), "r"(b[1]));
}
__device__ __forceinline__ float gelu_f(float u) {
    float t = 0.7978845608028654f * (u + 0.044715f * u * u * u);
    return 0.5f * u * (1.f + tanhf(t));
}

// ---------------------------------------------------------------------------
// Tensor-core GEMM, fp16 in, fp32 accumulate, single pass.
//   NT=false: C = A[M,K] @ B[K,N];  NT=true: C = alpha * A[M,K] @ B[N,K]^T
// EPI: 0 f32 *alpha | 1 h16(acc+bias) | 2 h16(gelu(acc+bias))
//      3 f32 acc+bias+R | 4 h16(acc)
// TRIK: limit K loop to m0+BM (PV with causal-zeroed probs; exact).
// 256 threads, 8 warps (BM/WM)x(BN/WN), BK=16, reg-staged double buffer.
// 2 CTAs/SM target. M%BM==0, K%16==0, (NN) N%BN==0; NT N guarded.
// ---------------------------------------------------------------------------
template<int BM, int BN, int WM, int WN, int EPI, bool NT, bool SKIP, bool TRIK>
__global__ __launch_bounds__(256, 2)
void gemm_tc(const h16* __restrict__ A, const h16* __restrict__ B,
             const float* __restrict__ bias, const float* __restrict__ R,
             float* __restrict__ Cf, h16* __restrict__ Ch,
             int M, int N, int K, int lda, int ldb, int ldc, float alpha,
             long aO, long aI, long bO, long bI, long cO, long cI, int innerCnt)
{
    constexpr int BK  = 16;
    constexpr int BKP = 24;        // padded k row stride (48B)
    constexpr int BNP = BN + 8;    // NN B row stride
    constexpr int WARPS_N = BN / WN;
    constexpr int MI = WM / 16, NF = WN / 8, NP = NF / 2;
    constexpr int ALD = (BM * BK / 4) / 256;     // uint2 loads per thread
    constexpr int BLD = (BN * BK / 4) / 256;
    static_assert((BM / WM) * (BN / WN) == 8, "8 warps");

    const int m0 = blockIdx.y * BM;
    const int n0 = blockIdx.x * BN;
    if (SKIP && n0 > m0 + BM - 1) return;

    if (innerCnt > 0) {
        int z = blockIdx.z, zo = z / innerCnt, zi = z % innerCnt;
        A += zo * aO + zi * aI;
        B += zo * bO + zi * bI;
        long co = zo * cO + zi * cI;
        if (Cf) Cf += co;
        if (Ch) Ch += co;
    }

    constexpr int ASZ = BM * BKP;                 // els
    constexpr int BSZ = NT ? BN * BKP : BK * BNP;
    __shared__ __align__(16) h16 sm[2 * (ASZ + BSZ)];

    const int tid = threadIdx.x, lane = tid & 31, w = tid >> 5;
    const int wm = w / WARPS_N, wn = w % WARPS_N;

    float acc[MI][NF][4];
#pragma unroll
    for (int i = 0; i < MI; i++)
#pragma unroll
        for (int j = 0; j < NF; j++)
#pragma unroll
            for (int q = 0; q < 4; q++) acc[i][j][q] = 0.f;

    uint2 pa[ALD], pb[BLD];

    auto loadG = [&](int t) {
#pragma unroll
        for (int j = 0; j < ALD; j++) {
            int i = tid + 256 * j;
            int r = i >> 2, kc = (i & 3) * 4;
            pa[j] = *(const uint2*)(A + (size_t)(m0 + r) * lda + t * BK + kc);
        }
#pragma unroll
        for (int j = 0; j < BLD; j++) {
            int i = tid + 256 * j;
            if (NT) {
                int nr = i >> 2, kc = (i & 3) * 4;
                if (n0 + nr < N)
                    pb[j] = *(const uint2*)(B + (size_t)(n0 + nr) * ldb + t * BK + kc);
                else
                    pb[j] = make_uint2(0u, 0u);
            } else {
                int kk = i / (BN / 4), nc = (i % (BN / 4)) * 4;
                pb[j] = *(const uint2*)(B + (size_t)(t * BK + kk) * ldb + n0 + nc);
            }
        }
    };

    auto storeS = [&](int buf) {
        h16* As = sm + buf * (ASZ + BSZ);
        h16* Bs = As + ASZ;
#pragma unroll
        for (int j = 0; j < ALD; j++) {
            int i = tid + 256 * j;
            int r = i >> 2, kc = (i & 3) * 4;
            *(uint2*)&As[r * BKP + kc] = pa[j];
        }
#pragma unroll
        for (int j = 0; j < BLD; j++) {
            int i = tid + 256 * j;
            if (NT) {
                int nr = i >> 2, kc = (i & 3) * 4;
                *(uint2*)&Bs[nr * BKP + kc] = pb[j];
            } else {
                int kk = i / (BN / 4), nc = (i % (BN / 4)) * 4;
                *(uint2*)&Bs[kk * BNP + nc] = pb[j];
            }
        }
    };

    const int Keff = TRIK ? ((m0 + BM < K) ? (m0 + BM) : K) : K;
    const int nt = Keff / BK;
    loadG(0);
    storeS(0);
    __syncthreads();

    for (int t = 0; t < nt; t++) {
        const int buf = t & 1;
        if (t + 1 < nt) loadG(t + 1);

        h16* As = sm + buf * (ASZ + BSZ);
        unsigned sA = (unsigned)__cvta_generic_to_shared(As);
        unsigned sB = sA + ASZ * 2;

        unsigned a[MI][4];
        {
            const int arow = lane & 15;
            const int acol = (lane >> 4) * 8;
#pragma unroll
            for (int mi = 0; mi < MI; mi++)
                ldsm_x4(sA + ((wm * WM + mi * 16 + arow) * BKP + acol) * 2, a[mi]);
        }
#pragma unroll
        for (int p = 0; p < NP; p++) {
            unsigned b[4];
            if (NT) {
                const int nrow = (lane & 7) | ((lane >> 4) << 3);
                const int kcol = ((lane >> 3) & 1) * 8;
                ldsm_x4(sB + ((wn * WN + p * 16 + nrow) * BKP + kcol) * 2, b);
            } else {
                const int krow = lane & 15;
                const int ncol = wn * WN + p * 16 + (lane >> 4) * 8;
                ldsm_x4_t(sB + (krow * BNP + ncol) * 2, b);
            }
#pragma unroll
            for (int mi = 0; mi < MI; mi++) {
                mma16816(acc[mi][2 * p],     a[mi], b);
                mma16816(acc[mi][2 * p + 1], a[mi], b + 2);
            }
        }

        if (t + 1 < nt) {
            storeS(buf ^ 1);
            __syncthreads();
        }
    }

    // epilogue
    const int g = lane >> 2, tg = lane & 3;
#pragma unroll
    for (int mi = 0; mi < MI; mi++) {
#pragma unroll
        for (int nf = 0; nf < NF; nf++) {
            int col = n0 + wn * WN + nf * 8 + tg * 2;
#pragma unroll
            for (int h = 0; h < 2; h++) {
                int row = m0 + wm * WM + mi * 16 + g + h * 8;
                float v0 = acc[mi][nf][2 * h];
                float v1 = acc[mi][nf][2 * h + 1];
                if (EPI == 0) {
                    v0 *= alpha; v1 *= alpha;
                    if (col     < N) Cf[(size_t)row * ldc + col]     = v0;
                    if (col + 1 < N) Cf[(size_t)row * ldc + col + 1] = v1;
                } else if (EPI == 3) {
                    size_t o = (size_t)row * ldc + col;
                    Cf[o]     = v0 + bias[col]     + R[o];
                    Cf[o + 1] = v1 + bias[col + 1] + R[o + 1];
                } else {
                    if (EPI == 1 || EPI == 2) { v0 += bias[col]; v1 += bias[col + 1]; }
                    if (EPI == 2) { v0 = gelu_f(v0); v1 = gelu_f(v1); }
                    size_t o = (size_t)row * ldc + col;
                    *(__half2*)&Ch[o] = __floats2half2_rn(v0, v1);
                }
            }
        }
    }
}

// ---------------------------------------------------------------------------
// fp32 -> fp16 array convert (n % 4 == 0)
// ---------------------------------------------------------------------------
__global__ void conv_arr(const float* __restrict__ s, h16* __restrict__ d, long n)
{
    long i = ((long)blockIdx.x * blockDim.x + threadIdx.x) * 4;
    if (i >= n) return;
    float4 v = *(const float4*)(s + i);
    __half2 a = __floats2half2_rn(v.x, v.y);
    __half2 b = __floats2half2_rn(v.z, v.w);
    *(uint2*)(d + i) = make_uint2(*(unsigned*)&a, *(unsigned*)&b);
}

// ---------------------------------------------------------------------------
// LayerNorm: fp32 in, fp16 out. One block per row.
// ---------------------------------------------------------------------------
__global__ void layernorm_k(const float* __restrict__ x, const float* __restrict__ g,
                            const float* __restrict__ b, h16* __restrict__ y)
{
    const int row = blockIdx.x;
    const float* xr = x + (size_t)row * CC;
    __shared__ float s1[256], s2[256];
    const int tid = threadIdx.x;
    float a = 0.f, sq = 0.f;
    for (int c = tid; c < CC; c += 256) { float v = xr[c]; a += v; sq += v * v; }
    s1[tid] = a; s2[tid] = sq; __syncthreads();
    for (int s = 128; s > 0; s >>= 1) {
        if (tid < s) { s1[tid] += s1[tid + s]; s2[tid] += s2[tid + s]; }
        __syncthreads();
    }
    const float mean = s1[0] / CC;
    const float var  = s2[0] / CC - mean * mean;
    const float rstd = rsqrtf(var + 1e-5f);
    for (int c = tid; c < CC; c += 256)
        y[(size_t)row * CC + c] = __float2half_rn((xr[c] - mean) * rstd * g[c] + b[c]);
}

// ---------------------------------------------------------------------------
// Causal softmax: fp32 scores in, fp16 probs out (zeros beyond diagonal).
// ---------------------------------------------------------------------------
__global__ void softmax_causal(const float* __restrict__ att, h16* __restrict__ p)
{
    const int t = blockIdx.x;
    const size_t ro = ((size_t)blockIdx.y * TT + t) * TT;
    const float* row = att + ro;
    const int n = t + 1;
    __shared__ float red[256];
    const int tid = threadIdx.x;

    float mx = -1e30f;
    for (int j = tid; j < n; j += 256) mx = fmaxf(mx, row[j]);
    red[tid] = mx; __syncthreads();
    for (int s = 128; s > 0; s >>= 1) {
        if (tid < s) red[tid] = fmaxf(red[tid], red[tid + s]);
        __syncthreads();
    }
    mx = red[0]; __syncthreads();

    float sum = 0.f;
    for (int j = tid; j < n; j += 256) sum += expf(row[j] - mx);
    red[tid] = sum; __syncthreads();
    for (int s = 128; s > 0; s >>= 1) {
        if (tid < s) red[tid] += red[tid + s];
        __syncthreads();
    }
    const float inv = 1.f / red[0];

    for (int j = tid; j < n; j += 256)
        p[ro + j] = __float2half_rn(expf(row[j] - mx) * inv);
    const h16 z = __float2half(0.f);
    for (int j = n + tid; j < TT; j += 256) p[ro + j] = z;
}

__global__ void embed_k(const int* __restrict__ tok, const float* __restrict__ wte,
                        const float* __restrict__ wpe, float* __restrict__ x)
{
    const int idx = blockIdx.x * blockDim.x + threadIdx.x;
    if (idx >= BT * CC) return;
    const int bt = idx / CC, c = idx % CC;
    const int t  = bt % TT;
    x[idx] = wte[(size_t)tok[bt] * CC + c] + wpe[(size_t)t * CC + c];
}

__global__ void nll_k(const float* __restrict__ logits, const int* __restrict__ target,
                      float* __restrict__ nll)
{
    const int bt = blockIdx.x;
    const float* row = logits + (size_t)bt * VV;
    __shared__ float red[256];
    const int tid = threadIdx.x;

    float mx = -1e30f;
    for (int j = tid; j < VV; j += 256) mx = fmaxf(mx, row[j]);
    red[tid] = mx; __syncthreads();
    for (int s = 128; s > 0; s >>= 1) {
        if (tid < s) red[tid] = fmaxf(red[tid], red[tid + s]);
        __syncthreads();
    }
    mx = red[0]; __syncthreads();

    float sum = 0.f;
    for (int j = tid; j < VV; j += 256) sum += expf(row[j] - mx);
    red[tid] = sum; __syncthreads();
    for (int s = 128; s > 0; s >>= 1) {
        if (tid < s) red[tid] += red[tid + s];
        __syncthreads();
    }
    if (tid == 0)
        nll[bt] = logf(red[0]) + mx - row[target[bt]];
}

__global__ void mean_k(const float* __restrict__ nll, float* __restrict__ out)
{
    __shared__ float red[256];
    const int tid = threadIdx.x;
    float s = 0.f;
    for (int i = tid; i < BT; i += 256) s += nll[i];
    red[tid] = s; __syncthreads();
    for (int st = 128; st > 0; st >>= 1) {
        if (tid < st) red[tid] += red[tid + st];
        __syncthreads();
    }
    if (tid == 0) out[0] = red[0] / (float)BT;
}

// ---------------------------------------------------------------------------
// Launch
// ---------------------------------------------------------------------------
extern "C" void kernel_launch(void* const* d_in, const int* in_sizes, int n_in,
                              void* d_out, int out_size)
{
    const int*   tokens = (const int*)  d_in[0];
    const int*   target = (const int*)  d_in[1];
    const float* wte    = (const float*)d_in[2];
    const float* wpe    = (const float*)d_in[3];
    const float* ln1_g  = (const float*)d_in[4];
    const float* ln1_b  = (const float*)d_in[5];
    const float* attn_w = (const float*)d_in[6];
    const float* attn_b = (const float*)d_in[7];
    const float* proj_w = (const float*)d_in[8];
    const float* proj_b = (const float*)d_in[9];
    const float* ln2_g  = (const float*)d_in[10];
    const float* ln2_b  = (const float*)d_in[11];
    const float* fc_w   = (const float*)d_in[12];
    const float* fc_b   = (const float*)d_in[13];
    const float* fc2_w  = (const float*)d_in[14];
    const float* fc2_b  = (const float*)d_in[15];
    const float* lnf_g  = (const float*)d_in[16];
    const float* lnf_b  = (const float*)d_in[17];
    float* out = (float*)d_out;

    float *x, *att, *nll;
    h16 *h, *q, *p, *y, *f, *aw, *pw, *fw, *f2, *wt;
    cudaGetSymbolAddress((void**)&x,   g_x);
    cudaGetSymbolAddress((void**)&att, g_att);
    cudaGetSymbolAddress((void**)&nll, g_nll);
    cudaGetSymbolAddress((void**)&h,   g_h);
    cudaGetSymbolAddress((void**)&q,   g_q);
    cudaGetSymbolAddress((void**)&p,   g_p);
    cudaGetSymbolAddress((void**)&y,   g_y);
    cudaGetSymbolAddress((void**)&f,   g_f);
    cudaGetSymbolAddress((void**)&aw,  g_aw);
    cudaGetSymbolAddress((void**)&pw,  g_pw);
    cudaGetSymbolAddress((void**)&fw,  g_fw);
    cudaGetSymbolAddress((void**)&f2,  g_f2);
    cudaGetSymbolAddress((void**)&wt,  g_wt);

    // convert weights to fp16 (each launch; ~200us)
    {
        long n1 = (long)NLYR * CC * C3;
        long n2 = (long)NLYR * CC * CC;
        long n3 = (long)NLYR * CC * C4;
        long n5 = (long)VV * CC;
        conv_arr<<<(unsigned)((n1/4 + 255)/256), 256>>>(attn_w, aw, n1);
        conv_arr<<<(unsigned)((n2/4 + 255)/256), 256>>>(proj_w, pw, n2);
        conv_arr<<<(unsigned)((n3/4 + 255)/256), 256>>>(fc_w,   fw, n3);
        conv_arr<<<(unsigned)((n3/4 + 255)/256), 256>>>(fc2_w,  f2, n3);
        conv_arr<<<(unsigned)((n5/4 + 255)/256), 256>>>(wte,    wt, n5);
    }

    embed_k<<<(BT * CC + 255) / 256, 256>>>(tokens, wte, wpe, x);

    const long L1M = (long)TT * TT;
    const long QB  = (long)TT * C3;

    for (int l = 0; l < NLYR; l++) {
        const h16* law = aw + (size_t)l * CC * C3;
        const h16* lpw = pw + (size_t)l * CC * CC;
        const h16* lfw = fw + (size_t)l * CC * C4;
        const h16* lf2 = f2 + (size_t)l * C4 * CC;
        const float* ab  = attn_b + (size_t)l * C3;
        const float* pb  = proj_b + (size_t)l * CC;
        const float* fb  = fc_b   + (size_t)l * C4;
        const float* f2b = fc2_b  + (size_t)l * CC;

        layernorm_k<<<BT, 256>>>(x, ln1_g + l * CC, ln1_b + l * CC, h);

        // QKV -> fp16 qkv
        gemm_tc<128,128,32,64,1,false,false,false><<<dim3(C3/128, BT/128), 256>>>(
            h, law, ab, nullptr, nullptr, q,
            BT, C3, CC, CC, C3, C3, 1.f, 0,0,0,0,0,0, 0);

        // scores (f32), causal block skip, batched over 48 heads
        gemm_tc<128,128,32,64,0,true,true,false><<<dim3(TT/128, TT/128, BHN), 256>>>(
            q, q + CC, nullptr, nullptr, att, nullptr,
            TT, TT, HDD, C3, C3, TT, 0.125f,
            QB, HDD, QB, HDD, (long)NHH * L1M, L1M, NHH);

        softmax_causal<<<dim3(TT, BHN), 256>>>(att, p);

        // y = P @ V  -> fp16 y  (K loop limited to m0+BM: exact, probs are 0 past diag)
        gemm_tc<128,64,32,32,4,false,false,true><<<dim3(1, TT/128, BHN), 256>>>(
            p, q + 2 * CC, nullptr, nullptr, nullptr, y,
            TT, HDD, TT, TT, C3, CC, 1.f,
            (long)NHH * L1M, L1M, QB, HDD, (long)TT * CC, HDD, NHH);

        // x = x + y @ pw + pb   (f32 residual)
        gemm_tc<128,128,32,64,3,false,false,false><<<dim3(CC/128, BT/128), 256>>>(
            y, lpw, pb, x, x, nullptr,
            BT, CC, CC, CC, CC, CC, 1.f, 0,0,0,0,0,0, 0);

        layernorm_k<<<BT, 256>>>(x, ln2_g + l * CC, ln2_b + l * CC, h);

        // fc + gelu -> fp16 fc
        gemm_tc<128,128,32,64,2,false,false,false><<<dim3(C4/128, BT/128), 256>>>(
            h, lfw, fb, nullptr, nullptr, f,
            BT, C4, CC, CC, C4, C4, 1.f, 0,0,0,0,0,0, 0);

        // x = x + fc @ f2w + f2b
        gemm_tc<128,128,32,64,3,false,false,false><<<dim3(CC/128, BT/128), 256>>>(
            f, lf2, f2b, x, x, nullptr,
            BT, CC, C4, C4, CC, CC, 1.f, 0,0,0,0,0,0, 0);
    }

    layernorm_k<<<BT, 256>>>(x, lnf_g, lnf_b, h);

    // logits = h @ wte^T (f32 out)
    gemm_tc<128,128,32,64,0,true,false,false><<<dim3((VV + 127) / 128, BT / 128), 256>>>(
        h, wt, nullptr, nullptr, out, nullptr,
        BT, VV, CC, CC, CC, VV, 1.f, 0,0,0,0,0,0, 0);

    nll_k<<<BT, 256>>>(out, target, nll);
    mean_k<<<1, 256>>>(nll, out + (out_size - 1));
}

// round 14
// speedup vs baseline: 3.1014x; 1.3125x over previous
#include <cuda_runtime.h>
#include <cuda_fp16.h>
#include <math.h>

// ---------------------------------------------------------------------------
// GPT-2 124M forward. Single-pass fp16 mma.sync GEMMs (fp32 accum) +
// fused flash-attention (QK^T -> online softmax -> PV, one kernel/layer).
// R13: attention chain fused; g_att / g_p scratch removed.
// B=4, T=1024, C=768, NH=12, HD=64, NL=12, V=50257
// ---------------------------------------------------------------------------

#define BB   4
#define TT   1024
#define BT   4096
#define CC   768
#define C3   2304
#define C4   3072
#define NHH  12
#define HDD  64
#define NLYR 12
#define VV   50257
#define BHN  48

typedef __half h16;

// fp32 scratch
__device__ float g_x  [(size_t)BT * CC];
__device__ float g_nll[BT];
// fp16 activations
__device__ h16 g_h [(size_t)BT * CC];
__device__ h16 g_q [(size_t)BT * C3];
__device__ h16 g_y [(size_t)BT * CC];
__device__ h16 g_f [(size_t)BT * C4];
// fp16 weights
__device__ h16 g_aw[(size_t)NLYR * CC * C3];
__device__ h16 g_pw[(size_t)NLYR * CC * CC];
__device__ h16 g_fw[(size_t)NLYR * CC * C4];
__device__ h16 g_f2[(size_t)NLYR * C4 * CC];
__device__ h16 g_wt[(size_t)VV * CC];

// ---------------------------------------------------------------------------
// helpers
// ---------------------------------------------------------------------------
__device__ __forceinline__ void ldsm_x4(unsigned a, unsigned* r) {
    asm volatile("ldmatrix.sync.aligned.m8n8.x4.shared.b16 {%0,%1,%2,%3},[%4];"
                 : "=r"(r[0]), "=r"(r[1]), "=r"(r[2]), "=r"(r[3]) : "r"(a));
}
__device__ __forceinline__ void ldsm_x4_t(unsigned a, unsigned* r) {
    asm volatile("ldmatrix.sync.aligned.m8n8.x4.trans.shared.b16 {%0,%1,%2,%3},[%4];"
                 : "=r"(r[0]), "=r"(r[1]), "=r"(r[2]), "=r"(r[3]) : "r"(a));
}
__device__ __forceinline__ void mma16816(float* c, const unsigned* a, const unsigned* b) {
    asm volatile("mma.sync.aligned.m16n8k16.row.col.f32.f16.f16.f32 "
                 "{%0,%1,%2,%3},{%4,%5,%6,%7},{%8,%9},{%0,%1,%2,%3};"
                 : "+f"(c[0]), "+f"(c[1]), "+f"(c[2]), "+f"(c[3])
                 : "r"(a[0]), "r"(a[1]), "r"(a[2]), "r"(a[3]), "r"(b[0]), "r"(b[1]));
}
__device__ __forceinline__ float gelu_f(float u) {
    float t = 0.7978845608028654f * (u + 0.044715f * u * u * u);
    return 0.5f * u * (1.f + tanhf(t));
}

// ---------------------------------------------------------------------------
// Tensor-core GEMM, fp16 in, fp32 accumulate, single pass.
//   NT=false: C = A[M,K] @ B[K,N];  NT=true: C = alpha * A[M,K] @ B[N,K]^T
// EPI: 0 f32 *alpha | 1 h16(acc+bias) | 2 h16(gelu(acc+bias))
//      3 f32 acc+bias+R | 4 h16(acc)
// 256 threads, 8 warps (BM/WM)x(BN/WN), BK=16, reg-staged double buffer.
// 2 CTAs/SM target. M%BM==0, K%16==0, (NN) N%BN==0; NT N guarded.
// ---------------------------------------------------------------------------
template<int BM, int BN, int WM, int WN, int EPI, bool NT, bool SKIP>
__global__ __launch_bounds__(256, 2)
void gemm_tc(const h16* __restrict__ A, const h16* __restrict__ B,
             const float* __restrict__ bias, const float* __restrict__ R,
             float* __restrict__ Cf, h16* __restrict__ Ch,
             int M, int N, int K, int lda, int ldb, int ldc, float alpha,
             long aO, long aI, long bO, long bI, long cO, long cI, int innerCnt)
{
    constexpr int BK  = 16;
    constexpr int BKP = 24;        // padded k row stride (48B)
    constexpr int BNP = BN + 8;    // NN B row stride
    constexpr int WARPS_N = BN / WN;
    constexpr int MI = WM / 16, NF = WN / 8, NP = NF / 2;
    constexpr int ALD = (BM * BK / 4) / 256;     // uint2 loads per thread
    constexpr int BLD = (BN * BK / 4) / 256;
    static_assert((BM / WM) * (BN / WN) == 8, "8 warps");

    const int m0 = blockIdx.y * BM;
    const int n0 = blockIdx.x * BN;
    if (SKIP && n0 > m0 + BM - 1) return;

    if (innerCnt > 0) {
        int z = blockIdx.z, zo = z / innerCnt, zi = z % innerCnt;
        A += zo * aO + zi * aI;
        B += zo * bO + zi * bI;
        long co = zo * cO + zi * cI;
        if (Cf) Cf += co;
        if (Ch) Ch += co;
    }

    constexpr int ASZ = BM * BKP;                 // els
    constexpr int BSZ = NT ? BN * BKP : BK * BNP;
    __shared__ __align__(16) h16 sm[2 * (ASZ + BSZ)];

    const int tid = threadIdx.x, lane = tid & 31, w = tid >> 5;
    const int wm = w / WARPS_N, wn = w % WARPS_N;

    float acc[MI][NF][4];
#pragma unroll
    for (int i = 0; i < MI; i++)
#pragma unroll
        for (int j = 0; j < NF; j++)
#pragma unroll
            for (int q = 0; q < 4; q++) acc[i][j][q] = 0.f;

    uint2 pa[ALD], pb[BLD];

    auto loadG = [&](int t) {
#pragma unroll
        for (int j = 0; j < ALD; j++) {
            int i = tid + 256 * j;
            int r = i >> 2, kc = (i & 3) * 4;
            pa[j] = *(const uint2*)(A + (size_t)(m0 + r) * lda + t * BK + kc);
        }
#pragma unroll
        for (int j = 0; j < BLD; j++) {
            int i = tid + 256 * j;
            if (NT) {
                int nr = i >> 2, kc = (i & 3) * 4;
                if (n0 + nr < N)
                    pb[j] = *(const uint2*)(B + (size_t)(n0 + nr) * ldb + t * BK + kc);
                else
                    pb[j] = make_uint2(0u, 0u);
            } else {
                int kk = i / (BN / 4), nc = (i % (BN / 4)) * 4;
                pb[j] = *(const uint2*)(B + (size_t)(t * BK + kk) * ldb + n0 + nc);
            }
        }
    };

    auto storeS = [&](int buf) {
        h16* As = sm + buf * (ASZ + BSZ);
        h16* Bs = As + ASZ;
#pragma unroll
        for (int j = 0; j < ALD; j++) {
            int i = tid + 256 * j;
            int r = i >> 2, kc = (i & 3) * 4;
            *(uint2*)&As[r * BKP + kc] = pa[j];
        }
#pragma unroll
        for (int j = 0; j < BLD; j++) {
            int i = tid + 256 * j;
            if (NT) {
                int nr = i >> 2, kc = (i & 3) * 4;
                *(uint2*)&Bs[nr * BKP + kc] = pb[j];
            } else {
                int kk = i / (BN / 4), nc = (i % (BN / 4)) * 4;
                *(uint2*)&Bs[kk * BNP + nc] = pb[j];
            }
        }
    };

    const int nt = K / BK;
    loadG(0);
    storeS(0);
    __syncthreads();

    for (int t = 0; t < nt; t++) {
        const int buf = t & 1;
        if (t + 1 < nt) loadG(t + 1);

        h16* As = sm + buf * (ASZ + BSZ);
        unsigned sA = (unsigned)__cvta_generic_to_shared(As);
        unsigned sB = sA + ASZ * 2;

        unsigned a[MI][4];
        {
            const int arow = lane & 15;
            const int acol = (lane >> 4) * 8;
#pragma unroll
            for (int mi = 0; mi < MI; mi++)
                ldsm_x4(sA + ((wm * WM + mi * 16 + arow) * BKP + acol) * 2, a[mi]);
        }
#pragma unroll
        for (int p = 0; p < NP; p++) {
            unsigned b[4];
            if (NT) {
                const int nrow = (lane & 7) | ((lane >> 4) << 3);
                const int kcol = ((lane >> 3) & 1) * 8;
                ldsm_x4(sB + ((wn * WN + p * 16 + nrow) * BKP + kcol) * 2, b);
            } else {
                const int krow = lane & 15;
                const int ncol = wn * WN + p * 16 + (lane >> 4) * 8;
                ldsm_x4_t(sB + (krow * BNP + ncol) * 2, b);
            }
#pragma unroll
            for (int mi = 0; mi < MI; mi++) {
                mma16816(acc[mi][2 * p],     a[mi], b);
                mma16816(acc[mi][2 * p + 1], a[mi], b + 2);
            }
        }

        if (t + 1 < nt) {
            storeS(buf ^ 1);
            __syncthreads();
        }
    }

    // epilogue
    const int g = lane >> 2, tg = lane & 3;
#pragma unroll
    for (int mi = 0; mi < MI; mi++) {
#pragma unroll
        for (int nf = 0; nf < NF; nf++) {
            int col = n0 + wn * WN + nf * 8 + tg * 2;
#pragma unroll
            for (int h = 0; h < 2; h++) {
                int row = m0 + wm * WM + mi * 16 + g + h * 8;
                float v0 = acc[mi][nf][2 * h];
                float v1 = acc[mi][nf][2 * h + 1];
                if (EPI == 0) {
                    v0 *= alpha; v1 *= alpha;
                    if (col     < N) Cf[(size_t)row * ldc + col]     = v0;
                    if (col + 1 < N) Cf[(size_t)row * ldc + col + 1] = v1;
                } else if (EPI == 3) {
                    size_t o = (size_t)row * ldc + col;
                    Cf[o]     = v0 + bias[col]     + R[o];
                    Cf[o + 1] = v1 + bias[col + 1] + R[o + 1];
                } else {
                    if (EPI == 1 || EPI == 2) { v0 += bias[col]; v1 += bias[col + 1]; }
                    if (EPI == 2) { v0 = gelu_f(v0); v1 = gelu_f(v1); }
                    size_t o = (size_t)row * ldc + col;
                    *(__half2*)&Ch[o] = __floats2half2_rn(v0, v1);
                }
            }
        }
    }
}

// ---------------------------------------------------------------------------
// Fused flash attention (causal). One CTA = 128 Q rows x one (b,h).
// 8 warps; warp owns 16 rows. Q A-frags in regs; K/V tiles 128x64 in smem.
// Online softmax in fp32; P repacked C-frag -> A-frag in registers.
// ---------------------------------------------------------------------------
__global__ void flash_attn(const h16* __restrict__ qkv, h16* __restrict__ y)
{
    const int mb = blockIdx.x;                 // Q row block (0..7)
    const int bh = blockIdx.y;                 // 0..47
    const int b  = bh / NHH, hh_ = bh % NHH;
    const int m0 = mb * 128;

    const h16* Qg = qkv + (size_t)b * TT * C3 + hh_ * HDD;   // row stride C3
    const h16* Kg = Qg + CC;
    const h16* Vg = Qg + 2 * CC;

    __shared__ __align__(16) h16 sK[128 * 72];
    __shared__ __align__(16) h16 sV[128 * 72];

    const int tid = threadIdx.x, lane = tid & 31, w = tid >> 5;
    const int g = lane >> 2, tg = lane & 3;

    // ---- stage Q block via sK, pull A-frags to registers ----
    for (int i = tid; i < 2048; i += 256) {
        int r = i >> 4, c = (i & 15) * 4;
        *(uint2*)&sK[r * 72 + c] = *(const uint2*)(Qg + (size_t)(m0 + r) * C3 + c);
    }
    __syncthreads();
    unsigned q[4][4];
    {
        unsigned sKa = (unsigned)__cvta_generic_to_shared(sK);
        const int arow = lane & 15;
        const int ac = (lane >> 4) * 8;
#pragma unroll
        for (int kk = 0; kk < 4; kk++)
            ldsm_x4(sKa + ((w * 16 + arow) * 72 + kk * 16 + ac) * 2, q[kk]);
    }

    float o[8][4];
#pragma unroll
    for (int i = 0; i < 8; i++)
#pragma unroll
        for (int e = 0; e < 4; e++) o[i][e] = 0.f;
    float m_r[2] = {-1e30f, -1e30f}, l_r[2] = {0.f, 0.f};

    for (int kb = 0; kb <= mb; kb++) {
        __syncthreads();   // previous-iter reads (and Q frag pull) done
        for (int i = tid; i < 2048; i += 256) {
            int r = i >> 4, c = (i & 15) * 4;
            size_t off = (size_t)(kb * 128 + r) * C3 + c;
            *(uint2*)&sK[r * 72 + c] = *(const uint2*)(Kg + off);
            *(uint2*)&sV[r * 72 + c] = *(const uint2*)(Vg + off);
        }
        __syncthreads();

        // S = Q @ K^T  (16 rows x 128 cols per warp)
        float s[16][4];
#pragma unroll
        for (int i = 0; i < 16; i++)
#pragma unroll
            for (int e = 0; e < 4; e++) s[i][e] = 0.f;

        unsigned sKa = (unsigned)__cvta_generic_to_shared(sK);
#pragma unroll
        for (int kk = 0; kk < 4; kk++) {
            const int nrow = (lane & 7) | ((lane >> 4) << 3);
            const int kcol = kk * 16 + ((lane >> 3) & 1) * 8;
#pragma unroll
            for (int p = 0; p < 8; p++) {
                unsigned bf[4];
                ldsm_x4(sKa + ((p * 16 + nrow) * 72 + kcol) * 2, bf);
                mma16816(s[2 * p],     q[kk], bf);
                mma16816(s[2 * p + 1], q[kk], bf + 2);
            }
        }

        // scale (+ causal mask on diagonal block)
        if (kb == mb) {
            const int rbase = m0 + w * 16 + g;
#pragma unroll
            for (int nf = 0; nf < 16; nf++)
#pragma unroll
                for (int e = 0; e < 4; e++) {
                    int row = rbase + (e >> 1) * 8;
                    int col = kb * 128 + nf * 8 + tg * 2 + (e & 1);
                    s[nf][e] = (col <= row) ? s[nf][e] * 0.125f : -1e30f;
                }
        } else {
#pragma unroll
            for (int nf = 0; nf < 16; nf++)
#pragma unroll
                for (int e = 0; e < 4; e++) s[nf][e] *= 0.125f;
        }

        // online softmax per row half (h2=0: row g, h2=1: row g+8)
#pragma unroll
        for (int h2 = 0; h2 < 2; h2++) {
            float mx = -1e30f;
#pragma unroll
            for (int nf = 0; nf < 16; nf++)
                mx = fmaxf(mx, fmaxf(s[nf][2 * h2], s[nf][2 * h2 + 1]));
            mx = fmaxf(mx, __shfl_xor_sync(0xffffffffu, mx, 1));
            mx = fmaxf(mx, __shfl_xor_sync(0xffffffffu, mx, 2));
            float mnew = fmaxf(m_r[h2], mx);
            float sf = expf(m_r[h2] - mnew);
            m_r[h2] = mnew;
            l_r[h2] *= sf;
#pragma unroll
            for (int nf = 0; nf < 8; nf++) { o[nf][2 * h2] *= sf; o[nf][2 * h2 + 1] *= sf; }
            float ls = 0.f;
#pragma unroll
            for (int nf = 0; nf < 16; nf++) {
                float p0 = expf(s[nf][2 * h2] - mnew);
                float p1 = expf(s[nf][2 * h2 + 1] - mnew);
                s[nf][2 * h2] = p0; s[nf][2 * h2 + 1] = p1;
                ls += p0 + p1;
            }
            ls += __shfl_xor_sync(0xffffffffu, ls, 1);
            ls += __shfl_xor_sync(0xffffffffu, ls, 2);
            l_r[h2] += ls;
        }

        // PV: P (C-frags) -> A-frags in regs, O += P @ V
        unsigned sVa = (unsigned)__cvta_generic_to_shared(sV);
#pragma unroll
        for (int kk = 0; kk < 8; kk++) {
            unsigned ap[4];
            __half2 t0 = __floats2half2_rn(s[2 * kk][0],     s[2 * kk][1]);
            __half2 t1 = __floats2half2_rn(s[2 * kk][2],     s[2 * kk][3]);
            __half2 t2 = __floats2half2_rn(s[2 * kk + 1][0], s[2 * kk + 1][1]);
            __half2 t3 = __floats2half2_rn(s[2 * kk + 1][2], s[2 * kk + 1][3]);
            ap[0] = *(unsigned*)&t0; ap[1] = *(unsigned*)&t1;
            ap[2] = *(unsigned*)&t2; ap[3] = *(unsigned*)&t3;
            const int krow = kk * 16 + (lane & 15);
            const int ncol = (lane >> 4) * 8;
#pragma unroll
            for (int po = 0; po < 4; po++) {
                unsigned bf[4];
                ldsm_x4_t(sVa + (krow * 72 + po * 16 + ncol) * 2, bf);
                mma16816(o[2 * po],     ap, bf);
                mma16816(o[2 * po + 1], ap, bf + 2);
            }
        }
    }

    // write O / l  -> y [BT, CC] at head column block
#pragma unroll
    for (int h2 = 0; h2 < 2; h2++) {
        float inv = 1.f / l_r[h2];
        int row = m0 + w * 16 + g + h2 * 8;
#pragma unroll
        for (int po = 0; po < 8; po++) {
            int col = hh_ * HDD + po * 8 + tg * 2;
            __half2 hv = __floats2half2_rn(o[po][2 * h2] * inv, o[po][2 * h2 + 1] * inv);
            *(__half2*)&y[(size_t)(b * TT + row) * CC + col] = hv;
        }
    }
}

// ---------------------------------------------------------------------------
// fp32 -> fp16 array convert (n % 4 == 0)
// ---------------------------------------------------------------------------
__global__ void conv_arr(const float* __restrict__ s, h16* __restrict__ d, long n)
{
    long i = ((long)blockIdx.x * blockDim.x + threadIdx.x) * 4;
    if (i >= n) return;
    float4 v = *(const float4*)(s + i);
    __half2 a = __floats2half2_rn(v.x, v.y);
    __half2 b = __floats2half2_rn(v.z, v.w);
    *(uint2*)(d + i) = make_uint2(*(unsigned*)&a, *(unsigned*)&b);
}

// ---------------------------------------------------------------------------
// LayerNorm: fp32 in, fp16 out. One block per row.
// ---------------------------------------------------------------------------
__global__ void layernorm_k(const float* __restrict__ x, const float* __restrict__ g,
                            const float* __restrict__ b, h16* __restrict__ y)
{
    const int row = blockIdx.x;
    const float* xr = x + (size_t)row * CC;
    __shared__ float s1[256], s2[256];
    const int tid = threadIdx.x;
    float a = 0.f, sq = 0.f;
    for (int c = tid; c < CC; c += 256) { float v = xr[c]; a += v; sq += v * v; }
    s1[tid] = a; s2[tid] = sq; __syncthreads();
    for (int s = 128; s > 0; s >>= 1) {
        if (tid < s) { s1[tid] += s1[tid + s]; s2[tid] += s2[tid + s]; }
        __syncthreads();
    }
    const float mean = s1[0] / CC;
    const float var  = s2[0] / CC - mean * mean;
    const float rstd = rsqrtf(var + 1e-5f);
    for (int c = tid; c < CC; c += 256)
        y[(size_t)row * CC + c] = __float2half_rn((xr[c] - mean) * rstd * g[c] + b[c]);
}

__global__ void embed_k(const int* __restrict__ tok, const float* __restrict__ wte,
                        const float* __restrict__ wpe, float* __restrict__ x)
{
    const int idx = blockIdx.x * blockDim.x + threadIdx.x;
    if (idx >= BT * CC) return;
    const int bt = idx / CC, c = idx % CC;
    const int t  = bt % TT;
    x[idx] = wte[(size_t)tok[bt] * CC + c] + wpe[(size_t)t * CC + c];
}

__global__ void nll_k(const float* __restrict__ logits, const int* __restrict__ target,
                      float* __restrict__ nll)
{
    const int bt = blockIdx.x;
    const float* row = logits + (size_t)bt * VV;
    __shared__ float red[256];
    const int tid = threadIdx.x;

    float mx = -1e30f;
    for (int j = tid; j < VV; j += 256) mx = fmaxf(mx, row[j]);
    red[tid] = mx; __syncthreads();
    for (int s = 128; s > 0; s >>= 1) {
        if (tid < s) red[tid] = fmaxf(red[tid], red[tid + s]);
        __syncthreads();
    }
    mx = red[0]; __syncthreads();

    float sum = 0.f;
    for (int j = tid; j < VV; j += 256) sum += expf(row[j] - mx);
    red[tid] = sum; __syncthreads();
    for (int s = 128; s > 0; s >>= 1) {
        if (tid < s) red[tid] += red[tid + s];
        __syncthreads();
    }
    if (tid == 0)
        nll[bt] = logf(red[0]) + mx - row[target[bt]];
}

__global__ void mean_k(const float* __restrict__ nll, float* __restrict__ out)
{
    __shared__ float red[256];
    const int tid = threadIdx.x;
    float s = 0.f;
    for (int i = tid; i < BT; i += 256) s += nll[i];
    red[tid] = s; __syncthreads();
    for (int st = 128; st > 0; st >>= 1) {
        if (tid < st) red[tid] += red[tid + st];
        __syncthreads();
    }
    if (tid == 0) out[0] = red[0] / (float)BT;
}

// ---------------------------------------------------------------------------
// Launch
// ---------------------------------------------------------------------------
extern "C" void kernel_launch(void* const* d_in, const int* in_sizes, int n_in,
                              void* d_out, int out_size)
{
    const int*   tokens = (const int*)  d_in[0];
    const int*   target = (const int*)  d_in[1];
    const float* wte    = (const float*)d_in[2];
    const float* wpe    = (const float*)d_in[3];
    const float* ln1_g  = (const float*)d_in[4];
    const float* ln1_b  = (const float*)d_in[5];
    const float* attn_w = (const float*)d_in[6];
    const float* attn_b = (const float*)d_in[7];
    const float* proj_w = (const float*)d_in[8];
    const float* proj_b = (const float*)d_in[9];
    const float* ln2_g  = (const float*)d_in[10];
    const float* ln2_b  = (const float*)d_in[11];
    const float* fc_w   = (const float*)d_in[12];
    const float* fc_b   = (const float*)d_in[13];
    const float* fc2_w  = (const float*)d_in[14];
    const float* fc2_b  = (const float*)d_in[15];
    const float* lnf_g  = (const float*)d_in[16];
    const float* lnf_b  = (const float*)d_in[17];
    float* out = (float*)d_out;

    float *x, *nll;
    h16 *h, *q, *y, *f, *aw, *pw, *fw, *f2, *wt;
    cudaGetSymbolAddress((void**)&x,   g_x);
    cudaGetSymbolAddress((void**)&nll, g_nll);
    cudaGetSymbolAddress((void**)&h,   g_h);
    cudaGetSymbolAddress((void**)&q,   g_q);
    cudaGetSymbolAddress((void**)&y,   g_y);
    cudaGetSymbolAddress((void**)&f,   g_f);
    cudaGetSymbolAddress((void**)&aw,  g_aw);
    cudaGetSymbolAddress((void**)&pw,  g_pw);
    cudaGetSymbolAddress((void**)&fw,  g_fw);
    cudaGetSymbolAddress((void**)&f2,  g_f2);
    cudaGetSymbolAddress((void**)&wt,  g_wt);

    // convert weights to fp16 (each launch; ~200us)
    {
        long n1 = (long)NLYR * CC * C3;
        long n2 = (long)NLYR * CC * CC;
        long n3 = (long)NLYR * CC * C4;
        long n5 = (long)VV * CC;
        conv_arr<<<(unsigned)((n1/4 + 255)/256), 256>>>(attn_w, aw, n1);
        conv_arr<<<(unsigned)((n2/4 + 255)/256), 256>>>(proj_w, pw, n2);
        conv_arr<<<(unsigned)((n3/4 + 255)/256), 256>>>(fc_w,   fw, n3);
        conv_arr<<<(unsigned)((n3/4 + 255)/256), 256>>>(fc2_w,  f2, n3);
        conv_arr<<<(unsigned)((n5/4 + 255)/256), 256>>>(wte,    wt, n5);
    }

    embed_k<<<(BT * CC + 255) / 256, 256>>>(tokens, wte, wpe, x);

    for (int l = 0; l < NLYR; l++) {
        const h16* law = aw + (size_t)l * CC * C3;
        const h16* lpw = pw + (size_t)l * CC * CC;
        const h16* lfw = fw + (size_t)l * CC * C4;
        const h16* lf2 = f2 + (size_t)l * C4 * CC;
        const float* ab  = attn_b + (size_t)l * C3;
        const float* pb  = proj_b + (size_t)l * CC;
        const float* fb  = fc_b   + (size_t)l * C4;
        const float* f2b = fc2_b  + (size_t)l * CC;

        layernorm_k<<<BT, 256>>>(x, ln1_g + l * CC, ln1_b + l * CC, h);

        // QKV -> fp16 qkv
        gemm_tc<128,128,32,64,1,false,false><<<dim3(C3/128, BT/128), 256>>>(
            h, law, ab, nullptr, nullptr, q,
            BT, C3, CC, CC, C3, C3, 1.f, 0,0,0,0,0,0, 0);

        // fused flash attention -> fp16 y
        flash_attn<<<dim3(TT/128, BHN), 256>>>(q, y);

        // x = x + y @ pw + pb   (f32 residual)
        gemm_tc<128,128,32,64,3,false,false><<<dim3(CC/128, BT/128), 256>>>(
            y, lpw, pb, x, x, nullptr,
            BT, CC, CC, CC, CC, CC, 1.f, 0,0,0,0,0,0, 0);

        layernorm_k<<<BT, 256>>>(x, ln2_g + l * CC, ln2_b + l * CC, h);

        // fc + gelu -> fp16 fc
        gemm_tc<128,128,32,64,2,false,false><<<dim3(C4/128, BT/128), 256>>>(
            h, lfw, fb, nullptr, nullptr, f,
            BT, C4, CC, CC, C4, C4, 1.f, 0,0,0,0,0,0, 0);

        // x = x + fc @ f2w + f2b
        gemm_tc<128,128,32,64,3,false,false><<<dim3(CC/128, BT/128), 256>>>(
            f, lf2, f2b, x, x, nullptr,
            BT, CC, C4, C4, CC, CC, 1.f, 0,0,0,0,0,0, 0);
    }

    layernorm_k<<<BT, 256>>>(x, lnf_g, lnf_b, h);

    // logits = h @ wte^T (f32 out)
    gemm_tc<128,128,32,64,0,true,false><<<dim3((VV + 127) / 128, BT / 128), 256>>>(
        h, wt, nullptr, nullptr, out, nullptr,
        BT, VV, CC, CC, CC, VV, 1.f, 0,0,0,0,0,0, 0);

    nll_k<<<BT, 256>>>(out, target, nll);
    mean_k<<<1, 256>>>(nll, out + (out_size - 1));
}